// round 4
// baseline (speedup 1.0000x reference)
#include <cuda_runtime.h>
#include <math.h>

// Problem dims
#define BB 4
#define SS 2048
#define EE 768
#define HH 3
#define HD 256
#define BH (BB*HH)        // 12
#define KT 8

// Scratch (device globals; no allocation allowed)
__device__ float g_Q[(size_t)BH*SS*HD];
__device__ float g_K[(size_t)BH*SS*HD];
__device__ float g_V[(size_t)BH*SS*HD];
__device__ float g_Hd[(size_t)BH*SS*HD];
__device__ float g_Sc[(size_t)BH*SS*SS];   // 201 MB score/prob buffer

// 8x8 micro-tile FMA step over one KT-deep smem tile
#define COMPUTE(buf)                                                     \
  _Pragma("unroll")                                                      \
  for (int k = 0; k < KT; k++) {                                         \
    float4 a0 = *(const float4*)&As[buf][k][ty8];                        \
    float4 a1 = *(const float4*)&As[buf][k][ty8+4];                      \
    float4 b0 = *(const float4*)&Bs[buf][k][tx8];                        \
    float4 b1 = *(const float4*)&Bs[buf][k][tx8+4];                      \
    float a[8] = {a0.x,a0.y,a0.z,a0.w,a1.x,a1.y,a1.z,a1.w};              \
    float b[8] = {b0.x,b0.y,b0.z,b0.w,b1.x,b1.y,b1.z,b1.w};              \
    _Pragma("unroll")                                                    \
    for (int i = 0; i < 8; i++)                                          \
      _Pragma("unroll")                                                  \
      for (int j = 0; j < 8; j++)                                        \
        acc[i][j] += a[i] * b[j];                                        \
  }

#define SCATTER_A(buf, v) \
  { As[buf][ac+0][ar]=v.x; As[buf][ac+1][ar]=v.y; As[buf][ac+2][ar]=v.z; As[buf][ac+3][ar]=v.w; }
#define SCATTER_B(buf, v) \
  { Bs[buf][ac+0][ar]=v.x; Bs[buf][ac+1][ar]=v.y; Bs[buf][ac+2][ar]=v.z; Bs[buf][ac+3][ar]=v.w; }

// ---------------------------------------------------------------------------
// Kernel 1: QKV projections.  grid = (2, 16, 36): z = t*12 + b*3 + h
// C[2048x256] = X[b][2048x768] @ W[h][768x256]
// ---------------------------------------------------------------------------
__global__ __launch_bounds__(256) void proj_kernel(
    const float* __restrict__ Xk, const float* __restrict__ Xv, const float* __restrict__ Xq,
    const float* __restrict__ Wk, const float* __restrict__ Wv, const float* __restrict__ Wq)
{
    int z  = blockIdx.z;
    int t  = z / BH;
    int bh = z % BH;
    int b  = bh / HH, h = bh % HH;

    const float* X = (t == 0) ? Xk : (t == 1) ? Xv : Xq;
    const float* W = (t == 0) ? Wk : (t == 1) ? Wv : Wq;
    float*     Out = (t == 0) ? g_K : (t == 1) ? g_V : g_Q;

    __shared__ float As[2][KT][128];
    __shared__ float Bs[2][KT][128];

    int tid = threadIdx.x;
    int m0 = blockIdx.y * 128, n0 = blockIdx.x * 128;
    int ty8 = (tid >> 4) << 3, tx8 = (tid & 15) << 3;
    int ar = tid & 127, ac = (tid >> 7) << 2;   // A: row-per-thread transpose scatter
    int bk = tid >> 5,  bn = (tid & 31) << 2;   // B: direct (k-major)

    const float* Arow = X + (size_t)b * SS * EE + (size_t)(m0 + ar) * EE + ac;
    const float* Brow = W + (size_t)h * EE * HD + (size_t)bk * HD + n0 + bn;

    float acc[8][8] = {};

    { float4 av = *(const float4*)&Arow[0]; SCATTER_A(0, av);
      *(float4*)&Bs[0][bk][bn] = *(const float4*)&Brow[0]; }
    __syncthreads();

    const int nk = EE / KT;  // 96
    for (int it = 0; it < nk; it++) {
        int buf = it & 1;
        float4 pa, pb;
        if (it + 1 < nk) {
            pa = *(const float4*)&Arow[(it + 1) * KT];
            pb = *(const float4*)&Brow[(size_t)(it + 1) * KT * HD];
        }
        COMPUTE(buf);
        if (it + 1 < nk) {
            SCATTER_A(buf ^ 1, pa);
            *(float4*)&Bs[buf ^ 1][bk][bn] = pb;
            __syncthreads();
        }
    }

    #pragma unroll
    for (int i = 0; i < 8; i++) {
        float* o = Out + ((size_t)bh * SS + m0 + ty8 + i) * HD + n0 + tx8;
        *(float4*)&o[0] = make_float4(acc[i][0], acc[i][1], acc[i][2], acc[i][3]);
        *(float4*)&o[4] = make_float4(acc[i][4], acc[i][5], acc[i][6], acc[i][7]);
    }
}

// ---------------------------------------------------------------------------
// Kernel 2: causal scores S = Q K^T / sqrt(S).  grid = (16, 16, 12)
// ---------------------------------------------------------------------------
__global__ __launch_bounds__(256) void score_kernel()
{
    int bh = blockIdx.z;
    int mt = blockIdx.y, nt = blockIdx.x;
    if (nt > mt) return;

    const float* Q = g_Q + (size_t)bh * SS * HD;
    const float* K = g_K + (size_t)bh * SS * HD;
    float*      Sp = g_Sc + (size_t)bh * SS * SS;

    __shared__ float As[2][KT][128];
    __shared__ float Bs[2][KT][128];

    int tid = threadIdx.x;
    int m0 = mt * 128, n0 = nt * 128;
    int ty8 = (tid >> 4) << 3, tx8 = (tid & 15) << 3;
    int ar = tid & 127, ac = (tid >> 7) << 2;

    const float* Qrow = Q + (size_t)(m0 + ar) * HD + ac;   // A transpose scatter
    const float* Krow = K + (size_t)(n0 + ar) * HD + ac;   // B transpose scatter

    float acc[8][8] = {};

    { float4 av = *(const float4*)&Qrow[0]; SCATTER_A(0, av);
      float4 bv = *(const float4*)&Krow[0]; SCATTER_B(0, bv); }
    __syncthreads();

    const int nk = HD / KT;  // 32
    for (int it = 0; it < nk; it++) {
        int buf = it & 1;
        float4 pa, pb;
        if (it + 1 < nk) {
            pa = *(const float4*)&Qrow[(it + 1) * KT];
            pb = *(const float4*)&Krow[(it + 1) * KT];
        }
        COMPUTE(buf);
        if (it + 1 < nk) {
            SCATTER_A(buf ^ 1, pa);
            SCATTER_B(buf ^ 1, pb);
            __syncthreads();
        }
    }

    const float inv_scale = 1.0f / sqrtf((float)SS);
    #pragma unroll
    for (int i = 0; i < 8; i++) {
        int gi = m0 + ty8 + i;
        #pragma unroll
        for (int jj = 0; jj < 8; jj += 4) {
            int gj = n0 + tx8 + jj;
            float4 v;
            v.x = (gj + 0 > gi) ? -3.0e38f : acc[i][jj + 0] * inv_scale;
            v.y = (gj + 1 > gi) ? -3.0e38f : acc[i][jj + 1] * inv_scale;
            v.z = (gj + 2 > gi) ? -3.0e38f : acc[i][jj + 2] * inv_scale;
            v.w = (gj + 3 > gi) ? -3.0e38f : acc[i][jj + 3] * inv_scale;
            *(float4*)&Sp[(size_t)gi * SS + gj] = v;
        }
    }
}

// ---------------------------------------------------------------------------
// Kernel 3: warp-per-row causal softmax.  Zero-fills to 128 alignment so the
// PV GEMM can include the full diagonal tile.
// ---------------------------------------------------------------------------
__global__ __launch_bounds__(256) void softmax_kernel()
{
    int gwarp = (blockIdx.x * blockDim.x + threadIdx.x) >> 5;
    int lane  = threadIdx.x & 31;
    if (gwarp >= BH * SS) return;

    int bh = gwarp / SS;
    int r  = gwarp % SS;
    float* sp = g_Sc + (size_t)bh * SS * SS + (size_t)r * SS;
    int n = r + 1;

    float mx = -3.0e38f;
    for (int j = lane; j < n; j += 32) mx = fmaxf(mx, sp[j]);
    #pragma unroll
    for (int o = 16; o; o >>= 1) mx = fmaxf(mx, __shfl_xor_sync(0xffffffffu, mx, o));

    float sum = 0.f;
    for (int j = lane; j < n; j += 32) sum += __expf(sp[j] - mx);
    #pragma unroll
    for (int o = 16; o; o >>= 1) sum += __shfl_xor_sync(0xffffffffu, sum, o);

    float inv = 1.0f / sum;
    for (int j = lane; j < n; j += 32) sp[j] = __expf(sp[j] - mx) * inv;

    int nceil = ((n + 127) & ~127);
    for (int j = n + lane; j < nceil; j += 32) sp[j] = 0.f;
}

// ---------------------------------------------------------------------------
// Kernel 4: O = P @ V with causal K-bound.  grid = (2, 16, 12)
// ---------------------------------------------------------------------------
__global__ __launch_bounds__(256) void av_kernel()
{
    int bh = blockIdx.z;
    int mt = blockIdx.y, nt = blockIdx.x;

    const float* P = g_Sc + (size_t)bh * SS * SS;
    const float* V = g_V  + (size_t)bh * SS * HD;
    float*       O = g_Hd + (size_t)bh * SS * HD;

    __shared__ float As[2][KT][128];
    __shared__ float Bs[2][KT][128];

    int tid = threadIdx.x;
    int m0 = mt * 128, n0 = nt * 128;
    int ty8 = (tid >> 4) << 3, tx8 = (tid & 15) << 3;
    int ar = tid & 127, ac = (tid >> 7) << 2;   // A (P): transpose scatter
    int bk = tid >> 5,  bn = (tid & 31) << 2;   // B (V): direct

    const float* Arow = P + (size_t)(m0 + ar) * SS + ac;
    const float* Brow = V + (size_t)bk * HD + n0 + bn;

    float acc[8][8] = {};

    { float4 av = *(const float4*)&Arow[0]; SCATTER_A(0, av);
      *(float4*)&Bs[0][bk][bn] = *(const float4*)&Brow[0]; }
    __syncthreads();

    const int nk = (mt + 1) * (128 / KT);   // causal bound
    for (int it = 0; it < nk; it++) {
        int buf = it & 1;
        float4 pa, pb;
        if (it + 1 < nk) {
            pa = *(const float4*)&Arow[(it + 1) * KT];
            pb = *(const float4*)&Brow[(size_t)(it + 1) * KT * HD];
        }
        COMPUTE(buf);
        if (it + 1 < nk) {
            SCATTER_A(buf ^ 1, pa);
            *(float4*)&Bs[buf ^ 1][bk][bn] = pb;
            __syncthreads();
        }
    }

    #pragma unroll
    for (int i = 0; i < 8; i++) {
        float* o = O + (size_t)(m0 + ty8 + i) * HD + n0 + tx8;
        *(float4*)&o[0] = make_float4(acc[i][0], acc[i][1], acc[i][2], acc[i][3]);
        *(float4*)&o[4] = make_float4(acc[i][4], acc[i][5], acc[i][6], acc[i][7]);
    }
}

// ---------------------------------------------------------------------------
// Kernel 5: Y = concat(heads) @ Wo + bo.  grid = (6, 64)
// M = B*S = 8192, N = 768, K = 768 (gathered from g_Hd head layout)
// ---------------------------------------------------------------------------
__global__ __launch_bounds__(256) void outproj_kernel(
    const float* __restrict__ Wo, const float* __restrict__ bo, float* __restrict__ Y)
{
    __shared__ float As[2][KT][128];
    __shared__ float Bs[2][KT][128];

    int tid = threadIdx.x;
    int m0 = blockIdx.y * 128, n0 = blockIdx.x * 128;
    int ty8 = (tid >> 4) << 3, tx8 = (tid & 15) << 3;
    int ar = tid & 127, ac = (tid >> 7) << 2;   // A: gathered transpose scatter
    int bk = tid >> 5,  bn = (tid & 31) << 2;   // B: direct

    // 128-row tile stays inside one batch (2048 % 128 == 0)
    int b  = m0 / SS;
    int q  = (m0 % SS) + ar;

    const float* Brow = Wo + (size_t)bk * EE + n0 + bn;

    float acc[8][8] = {};

    // gather fetch of A at k-column (kk + ac): head = k/256, feat = k%256
    #define FETCH_HD(kk) \
        (*(const float4*)&g_Hd[(((size_t)(b * HH + (((kk) + ac) >> 8))) * SS + q) * HD + (((kk) + ac) & 255)])

    { float4 av = FETCH_HD(0); SCATTER_A(0, av);
      *(float4*)&Bs[0][bk][bn] = *(const float4*)&Brow[0]; }
    __syncthreads();

    const int nk = EE / KT;  // 96
    for (int it = 0; it < nk; it++) {
        int buf = it & 1;
        float4 pa, pb;
        if (it + 1 < nk) {
            pa = FETCH_HD((it + 1) * KT);
            pb = *(const float4*)&Brow[(size_t)(it + 1) * KT * EE];
        }
        COMPUTE(buf);
        if (it + 1 < nk) {
            SCATTER_A(buf ^ 1, pa);
            *(float4*)&Bs[buf ^ 1][bk][bn] = pb;
            __syncthreads();
        }
    }
    #undef FETCH_HD

    float4 bias0 = *(const float4*)&bo[n0 + tx8];
    float4 bias1 = *(const float4*)&bo[n0 + tx8 + 4];
    #pragma unroll
    for (int i = 0; i < 8; i++) {
        float* y = Y + (size_t)(m0 + ty8 + i) * EE + n0 + tx8;
        *(float4*)&y[0] = make_float4(acc[i][0] + bias0.x, acc[i][1] + bias0.y,
                                      acc[i][2] + bias0.z, acc[i][3] + bias0.w);
        *(float4*)&y[4] = make_float4(acc[i][4] + bias1.x, acc[i][5] + bias1.y,
                                      acc[i][6] + bias1.z, acc[i][7] + bias1.w);
    }
}

// ---------------------------------------------------------------------------
extern "C" void kernel_launch(void* const* d_in, const int* in_sizes, int n_in,
                              void* d_out, int out_size)
{
    const float* Xk = (const float*)d_in[0];
    const float* Xv = (const float*)d_in[1];
    const float* Xq = (const float*)d_in[2];
    const float* Wk = (const float*)d_in[3];
    const float* Wv = (const float*)d_in[4];
    const float* Wq = (const float*)d_in[5];
    const float* Wo = (const float*)d_in[6];
    const float* bo = (const float*)d_in[7];
    float* out = (float*)d_out;

    proj_kernel<<<dim3(HD/128, SS/128, 3*BH), 256>>>(Xk, Xv, Xq, Wk, Wv, Wq);
    score_kernel<<<dim3(SS/128, SS/128, BH), 256>>>();
    softmax_kernel<<<(BH*SS + 7) / 8, 256>>>();
    av_kernel<<<dim3(HD/128, SS/128, BH), 256>>>();
    outproj_kernel<<<dim3(EE/128, (BB*SS)/128, 1), 256>>>(Wo, bo, out);
}

// round 7
// speedup vs baseline: 1.4590x; 1.4590x over previous
#include <cuda_runtime.h>
#include <cuda_bf16.h>
#include <math.h>
#include <stdint.h>

// Problem dims
#define BB 4
#define SS 2048
#define EE 768
#define HH 3
#define HD 256
#define BH (BB*HH)        // 12
#define KT 8

// ---------------- device scratch (no allocation allowed) -------------------
__device__ float g_Sc[(size_t)BH*SS*SS];   // fp32 scores (causal half used)
__device__ float g_Hd[(size_t)BH*SS*HD];   // fp32 attention output (heads)
// bf16 hi/lo split operands for tensor-core GEMMs
__device__ __align__(256) __nv_bfloat16 g_Qhi[(size_t)BH*SS*HD];
__device__ __align__(256) __nv_bfloat16 g_Qlo[(size_t)BH*SS*HD];
__device__ __align__(256) __nv_bfloat16 g_Khi[(size_t)BH*SS*HD];
__device__ __align__(256) __nv_bfloat16 g_Klo[(size_t)BH*SS*HD];
__device__ __align__(256) __nv_bfloat16 g_Vthi[(size_t)BH*HD*SS];  // V^T [bh][f][k]
__device__ __align__(256) __nv_bfloat16 g_Vtlo[(size_t)BH*HD*SS];
__device__ __align__(256) __nv_bfloat16 g_Phi[(size_t)BH*SS*SS];   // probs hi
__device__ __align__(256) __nv_bfloat16 g_Plo[(size_t)BH*SS*SS];   // probs lo

// =========================== mma.sync machinery ============================
#define CHUNK 32
#define OPSZ  8192      // bytes: one operand per buffer (2 k16-panels x 4KB)
#define BUFSZ 32768     // 4 operands
#define SMEM_MMA 65536  // double buffered

__device__ __forceinline__ uint32_t smem_u32(const void* p) {
    uint32_t a;
    asm("{ .reg .u64 t; cvta.to.shared.u64 t, %1; cvt.u32.u64 %0, t; }" : "=r"(a) : "l"(p));
    return a;
}
#define CP16(saddr, gptr) \
    asm volatile("cp.async.cg.shared.global [%0], [%1], 16;" :: "r"(saddr), "l"(gptr))
#define CP_COMMIT() asm volatile("cp.async.commit_group;" ::: "memory")
#define CP_WAIT(n)  asm volatile("cp.async.wait_group %0;" :: "n"(n) : "memory")

#define MMA(c, a, b) \
    asm volatile("mma.sync.aligned.m16n8k16.row.col.f32.bf16.bf16.f32 " \
        "{%0,%1,%2,%3}, {%4,%5,%6,%7}, {%8,%9}, {%0,%1,%2,%3};" \
        : "+f"((c)[0]), "+f"((c)[1]), "+f"((c)[2]), "+f"((c)[3]) \
        : "r"((a)[0]), "r"((a)[1]), "r"((a)[2]), "r"((a)[3]), \
          "r"((b)[0]), "r"((b)[1]))

// swizzled byte offset inside one [128][16]-bf16 panel (row stride 32B).
// 16B halves XOR'd with row bit 2 -> fragment loads hit 32 distinct banks.
__device__ __forceinline__ uint32_t swoff(int row, int colhalf, int t) {
    return (uint32_t)((row << 5) + (((colhalf ^ ((row >> 2) & 1))) << 4) + (t << 2));
}

// issue cp.async for one 128x32 chunk of all 4 operands into buffer `buf`
__device__ __forceinline__ void issue_chunk(uint32_t sb, int buf,
    const __nv_bfloat16* Ahi, const __nv_bfloat16* Alo, size_t lda,
    const __nv_bfloat16* Bhi, const __nv_bfloat16* Blo, size_t ldb,
    int kc, int tid)
{
    const __nv_bfloat16* gp[4] = {Ahi, Alo, Bhi, Blo};
    size_t lds_[4] = {lda, lda, ldb, ldb};
    #pragma unroll
    for (int op = 0; op < 4; op++) {
        #pragma unroll
        for (int i = 0; i < 2; i++) {
            int j = tid + (i << 8);
            int row = j >> 2, panel = (j >> 1) & 1, half = j & 1;
            const void* g = gp[op] + (size_t)row * lds_[op] + kc * CHUNK + panel * 16 + half * 8;
            uint32_t s = sb + buf * BUFSZ + op * OPSZ + panel * 4096
                       + (row << 5) + ((half ^ ((row >> 2) & 1)) << 4);
            CP16(s, g);
        }
    }
}

__device__ __forceinline__ void compute_chunk(char* sm, int buf, int wm, int wn,
                                              int g, int t, float acc[4][4][4])
{
    #pragma unroll
    for (int p = 0; p < 2; p++) {
        char* base = sm + buf * BUFSZ + p * 4096;
        char* pAh = base;
        char* pAl = base + OPSZ;
        char* pBh = base + 2 * OPSZ;
        char* pBl = base + 3 * OPSZ;
        uint32_t a[4][4], b[4][2];
        // A_hi frags
        #pragma unroll
        for (int mi = 0; mi < 4; mi++) {
            int r = wm + mi * 16 + g;
            a[mi][0] = *(const uint32_t*)(pAh + swoff(r,     0, t));
            a[mi][1] = *(const uint32_t*)(pAh + swoff(r + 8, 0, t));
            a[mi][2] = *(const uint32_t*)(pAh + swoff(r,     1, t));
            a[mi][3] = *(const uint32_t*)(pAh + swoff(r + 8, 1, t));
        }
        // B_hi frags
        #pragma unroll
        for (int ni = 0; ni < 4; ni++) {
            int r = wn + ni * 8 + g;
            b[ni][0] = *(const uint32_t*)(pBh + swoff(r, 0, t));
            b[ni][1] = *(const uint32_t*)(pBh + swoff(r, 1, t));
        }
        #pragma unroll
        for (int mi = 0; mi < 4; mi++)
            #pragma unroll
            for (int ni = 0; ni < 4; ni++) MMA(acc[mi][ni], a[mi], b[ni]);
        // A_hi x B_lo
        #pragma unroll
        for (int ni = 0; ni < 4; ni++) {
            int r = wn + ni * 8 + g;
            b[ni][0] = *(const uint32_t*)(pBl + swoff(r, 0, t));
            b[ni][1] = *(const uint32_t*)(pBl + swoff(r, 1, t));
        }
        #pragma unroll
        for (int mi = 0; mi < 4; mi++)
            #pragma unroll
            for (int ni = 0; ni < 4; ni++) MMA(acc[mi][ni], a[mi], b[ni]);
        // A_lo x B_hi
        #pragma unroll
        for (int mi = 0; mi < 4; mi++) {
            int r = wm + mi * 16 + g;
            a[mi][0] = *(const uint32_t*)(pAl + swoff(r,     0, t));
            a[mi][1] = *(const uint32_t*)(pAl + swoff(r + 8, 0, t));
            a[mi][2] = *(const uint32_t*)(pAl + swoff(r,     1, t));
            a[mi][3] = *(const uint32_t*)(pAl + swoff(r + 8, 1, t));
        }
        #pragma unroll
        for (int ni = 0; ni < 4; ni++) {
            int r = wn + ni * 8 + g;
            b[ni][0] = *(const uint32_t*)(pBh + swoff(r, 0, t));
            b[ni][1] = *(const uint32_t*)(pBh + swoff(r, 1, t));
        }
        #pragma unroll
        for (int mi = 0; mi < 4; mi++)
            #pragma unroll
            for (int ni = 0; ni < 4; ni++) MMA(acc[mi][ni], a[mi], b[ni]);
    }
}

__device__ __forceinline__ void mma_mainloop(char* sm, uint32_t sb,
    const __nv_bfloat16* Ahi, const __nv_bfloat16* Alo, size_t lda,
    const __nv_bfloat16* Bhi, const __nv_bfloat16* Blo, size_t ldb,
    int nkc, float acc[4][4][4], int tid)
{
    int wid = tid >> 5, lane = tid & 31, g = lane >> 2, t = lane & 3;
    int wm = (wid >> 2) << 6, wn = (wid & 3) << 5;

    issue_chunk(sb, 0, Ahi, Alo, lda, Bhi, Blo, ldb, 0, tid);
    CP_COMMIT();
    for (int kc = 0; kc < nkc; kc++) {
        int buf = kc & 1;
        if (kc + 1 < nkc) {
            issue_chunk(sb, buf ^ 1, Ahi, Alo, lda, Bhi, Blo, ldb, kc + 1, tid);
            CP_COMMIT();
            CP_WAIT(1);
        } else {
            CP_WAIT(0);
        }
        __syncthreads();
        compute_chunk(sm, buf, wm, wn, g, t, acc);
        __syncthreads();
    }
}

// ---------------------------------------------------------------------------
// Kernel 2 (TC): causal scores S = Q K^T / sqrt(S).  grid (16,16,12), 256 thr
// (No masking needed: softmax only reads j <= r.)
// ---------------------------------------------------------------------------
__global__ __launch_bounds__(256) void score_tc()
{
    int bh = blockIdx.z, mt = blockIdx.y, nt = blockIdx.x;
    if (nt > mt) return;
    extern __shared__ char sm[];
    uint32_t sb = smem_u32(sm);
    int tid = threadIdx.x;

    float acc[4][4][4] = {};
    size_t ao = ((size_t)bh * SS + (size_t)mt * 128) * HD;
    size_t bo_ = ((size_t)bh * SS + (size_t)nt * 128) * HD;
    mma_mainloop(sm, sb, g_Qhi + ao, g_Qlo + ao, HD,
                 g_Khi + bo_, g_Klo + bo_, HD, HD / CHUNK, acc, tid);

    int wid = tid >> 5, lane = tid & 31, g = lane >> 2, t = lane & 3;
    int wm = (wid >> 2) << 6, wn = (wid & 3) << 5;
    float* Sp = g_Sc + (size_t)bh * SS * SS;
    const float isc = 0.022097086912079608f;   // 1/sqrt(2048)

    #pragma unroll
    for (int mi = 0; mi < 4; mi++) {
        int gr = mt * 128 + wm + mi * 16 + g;
        #pragma unroll
        for (int ni = 0; ni < 4; ni++) {
            int gc = nt * 128 + wn + ni * 8 + 2 * t;
            *(float2*)&Sp[(size_t)gr * SS + gc] =
                make_float2(acc[mi][ni][0] * isc, acc[mi][ni][1] * isc);
            *(float2*)&Sp[(size_t)(gr + 8) * SS + gc] =
                make_float2(acc[mi][ni][2] * isc, acc[mi][ni][3] * isc);
        }
    }
}

// ---------------------------------------------------------------------------
// Kernel 4 (TC): O = P @ V^T-layout, causal K-bound.  grid (2,16,12), 256 thr
// ---------------------------------------------------------------------------
__global__ __launch_bounds__(256) void av_tc()
{
    int bh = blockIdx.z, mt = blockIdx.y, nt = blockIdx.x;
    extern __shared__ char sm[];
    uint32_t sb = smem_u32(sm);
    int tid = threadIdx.x;

    float acc[4][4][4] = {};
    size_t ao = ((size_t)bh * SS + (size_t)mt * 128) * SS;
    size_t bo_ = ((size_t)bh * HD + (size_t)nt * 128) * SS;
    mma_mainloop(sm, sb, g_Phi + ao, g_Plo + ao, SS,
                 g_Vthi + bo_, g_Vtlo + bo_, SS, (mt + 1) * (128 / CHUNK), acc, tid);

    int wid = tid >> 5, lane = tid & 31, g = lane >> 2, t = lane & 3;
    int wm = (wid >> 2) << 6, wn = (wid & 3) << 5;
    float* O = g_Hd + (size_t)bh * SS * HD;

    #pragma unroll
    for (int mi = 0; mi < 4; mi++) {
        int gr = mt * 128 + wm + mi * 16 + g;
        #pragma unroll
        for (int ni = 0; ni < 4; ni++) {
            int gc = nt * 128 + wn + ni * 8 + 2 * t;
            *(float2*)&O[(size_t)gr * HD + gc] = make_float2(acc[mi][ni][0], acc[mi][ni][1]);
            *(float2*)&O[(size_t)(gr + 8) * HD + gc] = make_float2(acc[mi][ni][2], acc[mi][ni][3]);
        }
    }
}

// ======================= SIMT GEMM machinery (proj/outproj) =================
#define COMPUTE(buf)                                                     \
  _Pragma("unroll")                                                      \
  for (int k = 0; k < KT; k++) {                                         \
    float4 a0 = *(const float4*)&As[buf][k][ty8];                        \
    float4 a1 = *(const float4*)&As[buf][k][ty8+4];                      \
    float4 b0 = *(const float4*)&Bs[buf][k][tx8];                        \
    float4 b1 = *(const float4*)&Bs[buf][k][tx8+4];                      \
    float a[8] = {a0.x,a0.y,a0.z,a0.w,a1.x,a1.y,a1.z,a1.w};              \
    float b[8] = {b0.x,b0.y,b0.z,b0.w,b1.x,b1.y,b1.z,b1.w};              \
    _Pragma("unroll")                                                    \
    for (int i = 0; i < 8; i++)                                          \
      _Pragma("unroll")                                                  \
      for (int j = 0; j < 8; j++)                                        \
        acc[i][j] += a[i] * b[j];                                        \
  }

#define SCATTER_A(buf, v) \
  { As[buf][ac+0][ar]=v.x; As[buf][ac+1][ar]=v.y; As[buf][ac+2][ar]=v.z; As[buf][ac+3][ar]=v.w; }

// ---------------------------------------------------------------------------
// Kernel 1: QKV projections -> bf16 hi/lo splits (V transposed).
// ---------------------------------------------------------------------------
__global__ __launch_bounds__(256) void proj_kernel(
    const float* __restrict__ Xk, const float* __restrict__ Xv, const float* __restrict__ Xq,
    const float* __restrict__ Wk, const float* __restrict__ Wv, const float* __restrict__ Wq)
{
    int z  = blockIdx.z;
    int t  = z / BH;
    int bh = z % BH;
    int b  = bh / HH, h = bh % HH;

    const float* X = (t == 0) ? Xk : (t == 1) ? Xv : Xq;
    const float* W = (t == 0) ? Wk : (t == 1) ? Wv : Wq;

    __shared__ float As[2][KT][128];
    __shared__ float Bs[2][KT][128];

    int tid = threadIdx.x;
    int m0 = blockIdx.y * 128, n0 = blockIdx.x * 128;
    int ty8 = (tid >> 4) << 3, tx8 = (tid & 15) << 3;
    int ar = tid & 127, ac = (tid >> 7) << 2;
    int bk = tid >> 5,  bn = (tid & 31) << 2;

    const float* Arow = X + (size_t)b * SS * EE + (size_t)(m0 + ar) * EE + ac;
    const float* Brow = W + (size_t)h * EE * HD + (size_t)bk * HD + n0 + bn;

    float acc[8][8] = {};

    { float4 av = *(const float4*)&Arow[0]; SCATTER_A(0, av);
      *(float4*)&Bs[0][bk][bn] = *(const float4*)&Brow[0]; }
    __syncthreads();

    const int nk = EE / KT;
    for (int it = 0; it < nk; it++) {
        int buf = it & 1;
        float4 pa, pb;
        if (it + 1 < nk) {
            pa = *(const float4*)&Arow[(it + 1) * KT];
            pb = *(const float4*)&Brow[(size_t)(it + 1) * KT * HD];
        }
        COMPUTE(buf);
        if (it + 1 < nk) {
            SCATTER_A(buf ^ 1, pa);
            *(float4*)&Bs[buf ^ 1][bk][bn] = pb;
            __syncthreads();
        }
    }

    if (t == 1) {
        // V: write transposed bf16 hi/lo  [bh][f][q]
        __align__(16) __nv_bfloat16 hi8[8], lo8[8];
        #pragma unroll
        for (int j = 0; j < 8; j++) {
            #pragma unroll
            for (int i = 0; i < 8; i++) {
                float x = acc[i][j];
                __nv_bfloat16 hv = __float2bfloat16(x);
                hi8[i] = hv;
                lo8[i] = __float2bfloat16(x - __bfloat162float(hv));
            }
            size_t o = ((size_t)bh * HD + n0 + tx8 + j) * SS + m0 + ty8;
            *(uint4*)&g_Vthi[o] = *(uint4*)hi8;
            *(uint4*)&g_Vtlo[o] = *(uint4*)lo8;
        }
    } else {
        __nv_bfloat16* Dh = (t == 0) ? g_Khi : g_Qhi;
        __nv_bfloat16* Dl = (t == 0) ? g_Klo : g_Qlo;
        __align__(16) __nv_bfloat16 hi8[8], lo8[8];
        #pragma unroll
        for (int i = 0; i < 8; i++) {
            #pragma unroll
            for (int j = 0; j < 8; j++) {
                float x = acc[i][j];
                __nv_bfloat16 hv = __float2bfloat16(x);
                hi8[j] = hv;
                lo8[j] = __float2bfloat16(x - __bfloat162float(hv));
            }
            size_t o = ((size_t)bh * SS + m0 + ty8 + i) * HD + n0 + tx8;
            *(uint4*)&Dh[o] = *(uint4*)hi8;
            *(uint4*)&Dl[o] = *(uint4*)lo8;
        }
    }
}

// ---------------------------------------------------------------------------
// Kernel 3: warp-per-row causal softmax -> bf16 hi/lo probs, 128-aligned fill
// ---------------------------------------------------------------------------
__global__ __launch_bounds__(256) void softmax_kernel()
{
    int gwarp = (blockIdx.x * blockDim.x + threadIdx.x) >> 5;
    int lane  = threadIdx.x & 31;
    if (gwarp >= BH * SS) return;

    int bh = gwarp / SS;
    int r  = gwarp % SS;
    const float* sp = g_Sc + (size_t)bh * SS * SS + (size_t)r * SS;
    size_t pb = (size_t)bh * SS * SS + (size_t)r * SS;
    int n = r + 1;

    float mx = -3.0e38f;
    for (int j = lane; j < n; j += 32) mx = fmaxf(mx, sp[j]);
    #pragma unroll
    for (int o = 16; o; o >>= 1) mx = fmaxf(mx, __shfl_xor_sync(0xffffffffu, mx, o));

    float sum = 0.f;
    for (int j = lane; j < n; j += 32) sum += __expf(sp[j] - mx);
    #pragma unroll
    for (int o = 16; o; o >>= 1) sum += __shfl_xor_sync(0xffffffffu, sum, o);

    float inv = 1.0f / sum;
    for (int j = lane; j < n; j += 32) {
        float p = __expf(sp[j] - mx) * inv;
        __nv_bfloat16 ph = __float2bfloat16(p);
        g_Phi[pb + j] = ph;
        g_Plo[pb + j] = __float2bfloat16(p - __bfloat162float(ph));
    }

    __nv_bfloat16 zz = __float2bfloat16(0.0f);
    int nceil = ((n + 127) & ~127);
    for (int j = n + lane; j < nceil; j += 32) { g_Phi[pb + j] = zz; g_Plo[pb + j] = zz; }
}

// ---------------------------------------------------------------------------
// Kernel 5: Y = concat(heads) @ Wo + bo.  grid = (6, 64)
// ---------------------------------------------------------------------------
__global__ __launch_bounds__(256) void outproj_kernel(
    const float* __restrict__ Wo, const float* __restrict__ bo, float* __restrict__ Y)
{
    __shared__ float As[2][KT][128];
    __shared__ float Bs[2][KT][128];

    int tid = threadIdx.x;
    int m0 = blockIdx.y * 128, n0 = blockIdx.x * 128;
    int ty8 = (tid >> 4) << 3, tx8 = (tid & 15) << 3;
    int ar = tid & 127, ac = (tid >> 7) << 2;
    int bk = tid >> 5,  bn = (tid & 31) << 2;

    int b  = m0 / SS;
    int q  = (m0 % SS) + ar;

    const float* Brow = Wo + (size_t)bk * EE + n0 + bn;

    float acc[8][8] = {};

    #define FETCH_HD(kk) \
        (*(const float4*)&g_Hd[(((size_t)(b * HH + (((kk) + ac) >> 8))) * SS + q) * HD + (((kk) + ac) & 255)])

    { float4 av = FETCH_HD(0); SCATTER_A(0, av);
      *(float4*)&Bs[0][bk][bn] = *(const float4*)&Brow[0]; }
    __syncthreads();

    const int nk = EE / KT;
    for (int it = 0; it < nk; it++) {
        int buf = it & 1;
        float4 pa, pb;
        if (it + 1 < nk) {
            pa = FETCH_HD((it + 1) * KT);
            pb = *(const float4*)&Brow[(size_t)(it + 1) * KT * EE];
        }
        COMPUTE(buf);
        if (it + 1 < nk) {
            SCATTER_A(buf ^ 1, pa);
            *(float4*)&Bs[buf ^ 1][bk][bn] = pb;
            __syncthreads();
        }
    }
    #undef FETCH_HD

    float4 bias0 = *(const float4*)&bo[n0 + tx8];
    float4 bias1 = *(const float4*)&bo[n0 + tx8 + 4];
    #pragma unroll
    for (int i = 0; i < 8; i++) {
        float* y = Y + (size_t)(m0 + ty8 + i) * EE + n0 + tx8;
        *(float4*)&y[0] = make_float4(acc[i][0] + bias0.x, acc[i][1] + bias0.y,
                                      acc[i][2] + bias0.z, acc[i][3] + bias0.w);
        *(float4*)&y[4] = make_float4(acc[i][4] + bias1.x, acc[i][5] + bias1.y,
                                      acc[i][6] + bias1.z, acc[i][7] + bias1.w);
    }
}

// ---------------------------------------------------------------------------
extern "C" void kernel_launch(void* const* d_in, const int* in_sizes, int n_in,
                              void* d_out, int out_size)
{
    const float* Xk = (const float*)d_in[0];
    const float* Xv = (const float*)d_in[1];
    const float* Xq = (const float*)d_in[2];
    const float* Wk = (const float*)d_in[3];
    const float* Wv = (const float*)d_in[4];
    const float* Wq = (const float*)d_in[5];
    const float* Wo = (const float*)d_in[6];
    const float* bo = (const float*)d_in[7];
    float* out = (float*)d_out;

    cudaFuncSetAttribute(score_tc, cudaFuncAttributeMaxDynamicSharedMemorySize, SMEM_MMA);
    cudaFuncSetAttribute(av_tc,    cudaFuncAttributeMaxDynamicSharedMemorySize, SMEM_MMA);

    proj_kernel<<<dim3(HD/128, SS/128, 3*BH), 256>>>(Xk, Xv, Xq, Wk, Wv, Wq);
    score_tc<<<dim3(SS/128, SS/128, BH), 256, SMEM_MMA>>>();
    softmax_kernel<<<(BH*SS + 7) / 8, 256>>>();
    av_tc<<<dim3(HD/128, SS/128, BH), 256, SMEM_MMA>>>();
    outproj_kernel<<<dim3(EE/128, (BB*SS)/128, 1), 256>>>(Wo, bo, out);
}

// round 9
// speedup vs baseline: 2.2428x; 1.5373x over previous
#include <cuda_runtime.h>
#include <cuda_bf16.h>
#include <math.h>
#include <stdint.h>

// Problem dims
#define BB 4
#define SS 2048
#define EE 768
#define HH 3
#define HD 256
#define BH (BB*HH)        // 12

// ---------------- device scratch (no allocation allowed) -------------------
__device__ float g_Sc[(size_t)BH*SS*SS];   // fp32 scores (causal half used)
// bf16 hi/lo split operands
__device__ __align__(256) __nv_bfloat16 g_Xhi[(size_t)3*BB*SS*EE];   // inputs [t][b][s][e]
__device__ __align__(256) __nv_bfloat16 g_Xlo[(size_t)3*BB*SS*EE];
__device__ __align__(256) __nv_bfloat16 g_Wthi[(size_t)3*HH*HD*EE]; // W^T [t][h][n][k]
__device__ __align__(256) __nv_bfloat16 g_Wtlo[(size_t)3*HH*HD*EE];
__device__ __align__(256) __nv_bfloat16 g_WoThi[(size_t)EE*EE];     // Wo^T [n][k]
__device__ __align__(256) __nv_bfloat16 g_WoTlo[(size_t)EE*EE];
__device__ __align__(256) __nv_bfloat16 g_Qhi[(size_t)BH*SS*HD];
__device__ __align__(256) __nv_bfloat16 g_Qlo[(size_t)BH*SS*HD];
__device__ __align__(256) __nv_bfloat16 g_Khi[(size_t)BH*SS*HD];
__device__ __align__(256) __nv_bfloat16 g_Klo[(size_t)BH*SS*HD];
__device__ __align__(256) __nv_bfloat16 g_Vthi[(size_t)BH*HD*SS];  // V^T [bh][f][k]
__device__ __align__(256) __nv_bfloat16 g_Vtlo[(size_t)BH*HD*SS];
__device__ __align__(256) __nv_bfloat16 g_Phi[(size_t)BH*SS*SS];   // probs hi
__device__ __align__(256) __nv_bfloat16 g_Plo[(size_t)BH*SS*SS];   // probs lo
__device__ __align__(256) __nv_bfloat16 g_Ohi[(size_t)BB*SS*EE];   // attn out concat
__device__ __align__(256) __nv_bfloat16 g_Olo[(size_t)BB*SS*EE];

__device__ __forceinline__ void splt(float x, __nv_bfloat16& h, __nv_bfloat16& l) {
    h = __float2bfloat16(x);
    l = __float2bfloat16(x - __bfloat162float(h));
}

// =========================== mma.sync machinery ============================
#define CHUNK 32
#define OPSZ  8192      // bytes: one operand per buffer (2 k16-panels x 4KB)
#define BUFSZ 32768     // 4 operands
#define SMEM_MMA 65536  // double buffered

__device__ __forceinline__ uint32_t smem_u32(const void* p) {
    uint32_t a;
    asm("{ .reg .u64 t; cvta.to.shared.u64 t, %1; cvt.u32.u64 %0, t; }" : "=r"(a) : "l"(p));
    return a;
}
#define CP16(saddr, gptr) \
    asm volatile("cp.async.cg.shared.global [%0], [%1], 16;" :: "r"(saddr), "l"(gptr))
#define CP_COMMIT() asm volatile("cp.async.commit_group;" ::: "memory")
#define CP_WAIT(n)  asm volatile("cp.async.wait_group %0;" :: "n"(n) : "memory")

#define MMA(c, a, b) \
    asm volatile("mma.sync.aligned.m16n8k16.row.col.f32.bf16.bf16.f32 " \
        "{%0,%1,%2,%3}, {%4,%5,%6,%7}, {%8,%9}, {%0,%1,%2,%3};" \
        : "+f"((c)[0]), "+f"((c)[1]), "+f"((c)[2]), "+f"((c)[3]) \
        : "r"((a)[0]), "r"((a)[1]), "r"((a)[2]), "r"((a)[3]), \
          "r"((b)[0]), "r"((b)[1]))

__device__ __forceinline__ uint32_t swoff(int row, int colhalf, int t) {
    return (uint32_t)((row << 5) + (((colhalf ^ ((row >> 2) & 1))) << 4) + (t << 2));
}

__device__ __forceinline__ void issue_chunk(uint32_t sb, int buf,
    const __nv_bfloat16* Ahi, const __nv_bfloat16* Alo, size_t lda,
    const __nv_bfloat16* Bhi, const __nv_bfloat16* Blo, size_t ldb,
    int kc, int tid)
{
    const __nv_bfloat16* gp[4] = {Ahi, Alo, Bhi, Blo};
    size_t lds_[4] = {lda, lda, ldb, ldb};
    #pragma unroll
    for (int op = 0; op < 4; op++) {
        #pragma unroll
        for (int i = 0; i < 2; i++) {
            int j = tid + (i << 8);
            int row = j >> 2, panel = (j >> 1) & 1, half = j & 1;
            const void* g = gp[op] + (size_t)row * lds_[op] + kc * CHUNK + panel * 16 + half * 8;
            uint32_t s = sb + buf * BUFSZ + op * OPSZ + panel * 4096
                       + (row << 5) + ((half ^ ((row >> 2) & 1)) << 4);
            CP16(s, g);
        }
    }
}

__device__ __forceinline__ void compute_chunk(char* sm, int buf, int wm, int wn,
                                              int g, int t, float acc[4][4][4])
{
    #pragma unroll
    for (int p = 0; p < 2; p++) {
        char* base = sm + buf * BUFSZ + p * 4096;
        char* pAh = base;
        char* pAl = base + OPSZ;
        char* pBh = base + 2 * OPSZ;
        char* pBl = base + 3 * OPSZ;
        uint32_t a[4][4], b[4][2];
        #pragma unroll
        for (int mi = 0; mi < 4; mi++) {
            int r = wm + mi * 16 + g;
            a[mi][0] = *(const uint32_t*)(pAh + swoff(r,     0, t));
            a[mi][1] = *(const uint32_t*)(pAh + swoff(r + 8, 0, t));
            a[mi][2] = *(const uint32_t*)(pAh + swoff(r,     1, t));
            a[mi][3] = *(const uint32_t*)(pAh + swoff(r + 8, 1, t));
        }
        #pragma unroll
        for (int ni = 0; ni < 4; ni++) {
            int r = wn + ni * 8 + g;
            b[ni][0] = *(const uint32_t*)(pBh + swoff(r, 0, t));
            b[ni][1] = *(const uint32_t*)(pBh + swoff(r, 1, t));
        }
        #pragma unroll
        for (int mi = 0; mi < 4; mi++)
            #pragma unroll
            for (int ni = 0; ni < 4; ni++) MMA(acc[mi][ni], a[mi], b[ni]);
        // A_hi x B_lo
        #pragma unroll
        for (int ni = 0; ni < 4; ni++) {
            int r = wn + ni * 8 + g;
            b[ni][0] = *(const uint32_t*)(pBl + swoff(r, 0, t));
            b[ni][1] = *(const uint32_t*)(pBl + swoff(r, 1, t));
        }
        #pragma unroll
        for (int mi = 0; mi < 4; mi++)
            #pragma unroll
            for (int ni = 0; ni < 4; ni++) MMA(acc[mi][ni], a[mi], b[ni]);
        // A_lo x B_hi
        #pragma unroll
        for (int mi = 0; mi < 4; mi++) {
            int r = wm + mi * 16 + g;
            a[mi][0] = *(const uint32_t*)(pAl + swoff(r,     0, t));
            a[mi][1] = *(const uint32_t*)(pAl + swoff(r + 8, 0, t));
            a[mi][2] = *(const uint32_t*)(pAl + swoff(r,     1, t));
            a[mi][3] = *(const uint32_t*)(pAl + swoff(r + 8, 1, t));
        }
        #pragma unroll
        for (int ni = 0; ni < 4; ni++) {
            int r = wn + ni * 8 + g;
            b[ni][0] = *(const uint32_t*)(pBh + swoff(r, 0, t));
            b[ni][1] = *(const uint32_t*)(pBh + swoff(r, 1, t));
        }
        #pragma unroll
        for (int mi = 0; mi < 4; mi++)
            #pragma unroll
            for (int ni = 0; ni < 4; ni++) MMA(acc[mi][ni], a[mi], b[ni]);
    }
}

__device__ __forceinline__ void mma_mainloop(char* sm, uint32_t sb,
    const __nv_bfloat16* Ahi, const __nv_bfloat16* Alo, size_t lda,
    const __nv_bfloat16* Bhi, const __nv_bfloat16* Blo, size_t ldb,
    int nkc, float acc[4][4][4], int tid)
{
    int wid = tid >> 5, lane = tid & 31, g = lane >> 2, t = lane & 3;
    int wm = (wid >> 2) << 6, wn = (wid & 3) << 5;

    issue_chunk(sb, 0, Ahi, Alo, lda, Bhi, Blo, ldb, 0, tid);
    CP_COMMIT();
    for (int kc = 0; kc < nkc; kc++) {
        int buf = kc & 1;
        if (kc + 1 < nkc) {
            issue_chunk(sb, buf ^ 1, Ahi, Alo, lda, Bhi, Blo, ldb, kc + 1, tid);
            CP_COMMIT();
            CP_WAIT(1);
        } else {
            CP_WAIT(0);
        }
        __syncthreads();
        compute_chunk(sm, buf, wm, wn, g, t, acc);
        __syncthreads();
    }
}

// ---------------------------------------------------------------------------
// Split kernels (fp32 -> bf16 hi/lo)
// ---------------------------------------------------------------------------
__global__ __launch_bounds__(256) void split_x(
    const float* __restrict__ Xk, const float* __restrict__ Xv, const float* __restrict__ Xq)
{
    const size_t N4 = (size_t)BB * SS * EE / 4;
    size_t i = (size_t)blockIdx.x * blockDim.x + threadIdx.x;
    if (i >= 3 * N4) return;
    int t = (int)(i / N4);
    size_t j = (i % N4) * 4;
    const float* X = (t == 0) ? Xk : (t == 1) ? Xv : Xq;
    float4 v = *(const float4*)(X + j);
    __nv_bfloat16 h[4], l[4];
    splt(v.x, h[0], l[0]); splt(v.y, h[1], l[1]);
    splt(v.z, h[2], l[2]); splt(v.w, h[3], l[3]);
    size_t o = (size_t)t * BB * SS * EE + j;
    *(uint2*)&g_Xhi[o] = *(uint2*)h;
    *(uint2*)&g_Xlo[o] = *(uint2*)l;
}

__global__ __launch_bounds__(256) void split_w(
    const float* __restrict__ Wk, const float* __restrict__ Wv, const float* __restrict__ Wq)
{
    size_t id = (size_t)blockIdx.x * blockDim.x + threadIdx.x;
    const size_t tot = (size_t)3 * HH * HD * EE;
    if (id >= tot) return;
    int k = (int)(id % EE);
    int n = (int)((id / EE) % HD);
    int h = (int)((id / ((size_t)EE * HD)) % HH);
    int t = (int)(id / ((size_t)EE * HD * HH));
    const float* W = (t == 0) ? Wk : (t == 1) ? Wv : Wq;
    float x = __ldg(&W[(size_t)h * EE * HD + (size_t)k * HD + n]);
    splt(x, g_Wthi[id], g_Wtlo[id]);
}

__global__ __launch_bounds__(256) void split_wo(const float* __restrict__ Wo)
{
    size_t id = (size_t)blockIdx.x * blockDim.x + threadIdx.x;
    if (id >= (size_t)EE * EE) return;
    int k = (int)(id % EE), n = (int)(id / EE);
    float x = __ldg(&Wo[(size_t)k * EE + n]);
    splt(x, g_WoThi[id], g_WoTlo[id]);
}

// ---------------------------------------------------------------------------
// Kernel 1 (TC): QKV projections.  grid (2, 16, 36): z = t*12 + bh
// ---------------------------------------------------------------------------
__global__ __launch_bounds__(256) void proj_tc(int dummy)
{
    int z = blockIdx.z, nt = blockIdx.x, mt = blockIdx.y;
    int t = z / BH, bh = z % BH;
    int b = bh / HH, h = bh % HH;
    extern __shared__ char sm[];
    uint32_t sb = smem_u32(sm);
    int tid = threadIdx.x;

    float acc[4][4][4] = {};
    const __nv_bfloat16* Ahi = g_Xhi + ((size_t)t * BB + b) * SS * EE + (size_t)mt * 128 * EE;
    const __nv_bfloat16* Alo = g_Xlo + ((size_t)t * BB + b) * SS * EE + (size_t)mt * 128 * EE;
    const __nv_bfloat16* Bhi = g_Wthi + (((size_t)t * HH + h) * HD + (size_t)nt * 128) * EE;
    const __nv_bfloat16* Blo = g_Wtlo + (((size_t)t * HH + h) * HD + (size_t)nt * 128) * EE;
    mma_mainloop(sm, sb, Ahi, Alo, EE, Bhi, Blo, EE, EE / CHUNK, acc, tid);

    int wid = tid >> 5, lane = tid & 31, g = lane >> 2, tq = lane & 3;
    int wm = (wid >> 2) << 6, wn = (wid & 3) << 5;

    if (t == 1) {
        // V: transposed bf16 hi/lo [bh][f][q]
        __nv_bfloat16* Vh = g_Vthi + (size_t)bh * HD * SS;
        __nv_bfloat16* Vl = g_Vtlo + (size_t)bh * HD * SS;
        #pragma unroll
        for (int mi = 0; mi < 4; mi++) {
            int q = mt * 128 + wm + mi * 16 + g;
            #pragma unroll
            for (int ni = 0; ni < 4; ni++) {
                int f = nt * 128 + wn + ni * 8 + 2 * tq;
                __nv_bfloat16 hh, ll;
                splt(acc[mi][ni][0], hh, ll); Vh[(size_t)f*SS + q] = hh; Vl[(size_t)f*SS + q] = ll;
                splt(acc[mi][ni][1], hh, ll); Vh[(size_t)(f+1)*SS + q] = hh; Vl[(size_t)(f+1)*SS + q] = ll;
                splt(acc[mi][ni][2], hh, ll); Vh[(size_t)f*SS + q + 8] = hh; Vl[(size_t)f*SS + q + 8] = ll;
                splt(acc[mi][ni][3], hh, ll); Vh[(size_t)(f+1)*SS + q + 8] = hh; Vl[(size_t)(f+1)*SS + q + 8] = ll;
            }
        }
    } else {
        __nv_bfloat16* Dh = ((t == 0) ? g_Khi : g_Qhi) + (size_t)bh * SS * HD;
        __nv_bfloat16* Dl = ((t == 0) ? g_Klo : g_Qlo) + (size_t)bh * SS * HD;
        #pragma unroll
        for (int mi = 0; mi < 4; mi++) {
            int s = mt * 128 + wm + mi * 16 + g;
            #pragma unroll
            for (int ni = 0; ni < 4; ni++) {
                int f = nt * 128 + wn + ni * 8 + 2 * tq;
                __nv_bfloat162 hp, lp;
                splt(acc[mi][ni][0], hp.x, lp.x); splt(acc[mi][ni][1], hp.y, lp.y);
                *(__nv_bfloat162*)&Dh[(size_t)s * HD + f] = hp;
                *(__nv_bfloat162*)&Dl[(size_t)s * HD + f] = lp;
                splt(acc[mi][ni][2], hp.x, lp.x); splt(acc[mi][ni][3], hp.y, lp.y);
                *(__nv_bfloat162*)&Dh[(size_t)(s + 8) * HD + f] = hp;
                *(__nv_bfloat162*)&Dl[(size_t)(s + 8) * HD + f] = lp;
            }
        }
    }
}

// ---------------------------------------------------------------------------
// Kernel 2 (TC): causal scores S = Q K^T / sqrt(S).  grid (16,16,12)
// ---------------------------------------------------------------------------
__global__ __launch_bounds__(256) void score_tc()
{
    int bh = blockIdx.z, mt = blockIdx.y, nt = blockIdx.x;
    if (nt > mt) return;
    extern __shared__ char sm[];
    uint32_t sb = smem_u32(sm);
    int tid = threadIdx.x;

    float acc[4][4][4] = {};
    size_t ao = ((size_t)bh * SS + (size_t)mt * 128) * HD;
    size_t bo_ = ((size_t)bh * SS + (size_t)nt * 128) * HD;
    mma_mainloop(sm, sb, g_Qhi + ao, g_Qlo + ao, HD,
                 g_Khi + bo_, g_Klo + bo_, HD, HD / CHUNK, acc, tid);

    int wid = tid >> 5, lane = tid & 31, g = lane >> 2, t = lane & 3;
    int wm = (wid >> 2) << 6, wn = (wid & 3) << 5;
    float* Sp = g_Sc + (size_t)bh * SS * SS;
    const float isc = 0.022097086912079608f;   // 1/sqrt(2048)

    #pragma unroll
    for (int mi = 0; mi < 4; mi++) {
        int gr = mt * 128 + wm + mi * 16 + g;
        #pragma unroll
        for (int ni = 0; ni < 4; ni++) {
            int gc = nt * 128 + wn + ni * 8 + 2 * t;
            *(float2*)&Sp[(size_t)gr * SS + gc] =
                make_float2(acc[mi][ni][0] * isc, acc[mi][ni][1] * isc);
            *(float2*)&Sp[(size_t)(gr + 8) * SS + gc] =
                make_float2(acc[mi][ni][2] * isc, acc[mi][ni][3] * isc);
        }
    }
}

// ---------------------------------------------------------------------------
// Kernel 3: warp-per-row causal softmax -> bf16 hi/lo probs, 128-aligned fill
// ---------------------------------------------------------------------------
__global__ __launch_bounds__(256) void softmax_kernel()
{
    int gwarp = (blockIdx.x * blockDim.x + threadIdx.x) >> 5;
    int lane  = threadIdx.x & 31;
    if (gwarp >= BH * SS) return;

    int bh = gwarp / SS;
    int r  = gwarp % SS;
    const float* sp = g_Sc + (size_t)bh * SS * SS + (size_t)r * SS;
    size_t pb = (size_t)bh * SS * SS + (size_t)r * SS;
    int n = r + 1;

    float mx = -3.0e38f;
    for (int j = lane; j < n; j += 32) mx = fmaxf(mx, sp[j]);
    #pragma unroll
    for (int o = 16; o; o >>= 1) mx = fmaxf(mx, __shfl_xor_sync(0xffffffffu, mx, o));

    float sum = 0.f;
    for (int j = lane; j < n; j += 32) sum += __expf(sp[j] - mx);
    #pragma unroll
    for (int o = 16; o; o >>= 1) sum += __shfl_xor_sync(0xffffffffu, sum, o);

    float inv = 1.0f / sum;
    for (int j = lane; j < n; j += 32) {
        float p = __expf(sp[j] - mx) * inv;
        splt(p, g_Phi[pb + j], g_Plo[pb + j]);
    }

    __nv_bfloat16 zz = __float2bfloat16(0.0f);
    int nceil = ((n + 127) & ~127);
    for (int j = n + lane; j < nceil; j += 32) { g_Phi[pb + j] = zz; g_Plo[pb + j] = zz; }
}

// ---------------------------------------------------------------------------
// Kernel 4 (TC): O = P @ V^T-layout, causal K-bound -> concat bf16 hi/lo.
// grid (2,16,12)
// ---------------------------------------------------------------------------
__global__ __launch_bounds__(256) void av_tc()
{
    int bh = blockIdx.z, mt = blockIdx.y, nt = blockIdx.x;
    extern __shared__ char sm[];
    uint32_t sb = smem_u32(sm);
    int tid = threadIdx.x;

    float acc[4][4][4] = {};
    size_t ao = ((size_t)bh * SS + (size_t)mt * 128) * SS;
    size_t bo_ = ((size_t)bh * HD + (size_t)nt * 128) * SS;
    mma_mainloop(sm, sb, g_Phi + ao, g_Plo + ao, SS,
                 g_Vthi + bo_, g_Vtlo + bo_, SS, (mt + 1) * (128 / CHUNK), acc, tid);

    int wid = tid >> 5, lane = tid & 31, g = lane >> 2, t = lane & 3;
    int wm = (wid >> 2) << 6, wn = (wid & 3) << 5;
    int b = bh / HH, h = bh % HH;

    #pragma unroll
    for (int mi = 0; mi < 4; mi++) {
        size_t row = (size_t)b * SS + mt * 128 + wm + mi * 16 + g;
        #pragma unroll
        for (int ni = 0; ni < 4; ni++) {
            int col = h * HD + nt * 128 + wn + ni * 8 + 2 * t;
            __nv_bfloat162 hp, lp;
            splt(acc[mi][ni][0], hp.x, lp.x); splt(acc[mi][ni][1], hp.y, lp.y);
            *(__nv_bfloat162*)&g_Ohi[row * EE + col] = hp;
            *(__nv_bfloat162*)&g_Olo[row * EE + col] = lp;
            splt(acc[mi][ni][2], hp.x, lp.x); splt(acc[mi][ni][3], hp.y, lp.y);
            *(__nv_bfloat162*)&g_Ohi[(row + 8) * EE + col] = hp;
            *(__nv_bfloat162*)&g_Olo[(row + 8) * EE + col] = lp;
        }
    }
}

// ---------------------------------------------------------------------------
// Kernel 5 (TC): Y = concat @ Wo + bo.  grid (6, 64)
// ---------------------------------------------------------------------------
__global__ __launch_bounds__(256) void outproj_tc(
    const float* __restrict__ bo, float* __restrict__ Y)
{
    int nt = blockIdx.x, mt = blockIdx.y;
    extern __shared__ char sm[];
    uint32_t sb = smem_u32(sm);
    int tid = threadIdx.x;

    float acc[4][4][4] = {};
    const __nv_bfloat16* Ahi = g_Ohi + (size_t)mt * 128 * EE;
    const __nv_bfloat16* Alo = g_Olo + (size_t)mt * 128 * EE;
    const __nv_bfloat16* Bhi = g_WoThi + (size_t)nt * 128 * EE;
    const __nv_bfloat16* Blo = g_WoTlo + (size_t)nt * 128 * EE;
    mma_mainloop(sm, sb, Ahi, Alo, EE, Bhi, Blo, EE, EE / CHUNK, acc, tid);

    int wid = tid >> 5, lane = tid & 31, g = lane >> 2, t = lane & 3;
    int wm = (wid >> 2) << 6, wn = (wid & 3) << 5;

    #pragma unroll
    for (int mi = 0; mi < 4; mi++) {
        size_t gr = (size_t)mt * 128 + wm + mi * 16 + g;
        #pragma unroll
        for (int ni = 0; ni < 4; ni++) {
            int gc = nt * 128 + wn + ni * 8 + 2 * t;
            float bx = bo[gc], by = bo[gc + 1];
            *(float2*)&Y[gr * EE + gc] =
                make_float2(acc[mi][ni][0] + bx, acc[mi][ni][1] + by);
            *(float2*)&Y[(gr + 8) * EE + gc] =
                make_float2(acc[mi][ni][2] + bx, acc[mi][ni][3] + by);
        }
    }
}

// ---------------------------------------------------------------------------
extern "C" void kernel_launch(void* const* d_in, const int* in_sizes, int n_in,
                              void* d_out, int out_size)
{
    const float* Xk = (const float*)d_in[0];
    const float* Xv = (const float*)d_in[1];
    const float* Xq = (const float*)d_in[2];
    const float* Wk = (const float*)d_in[3];
    const float* Wv = (const float*)d_in[4];
    const float* Wq = (const float*)d_in[5];
    const float* Wo = (const float*)d_in[6];
    const float* bo = (const float*)d_in[7];
    float* out = (float*)d_out;

    cudaFuncSetAttribute(proj_tc,    cudaFuncAttributeMaxDynamicSharedMemorySize, SMEM_MMA);
    cudaFuncSetAttribute(score_tc,   cudaFuncAttributeMaxDynamicSharedMemorySize, SMEM_MMA);
    cudaFuncSetAttribute(av_tc,      cudaFuncAttributeMaxDynamicSharedMemorySize, SMEM_MMA);
    cudaFuncSetAttribute(outproj_tc, cudaFuncAttributeMaxDynamicSharedMemorySize, SMEM_MMA);

    {   // splits
        size_t nx = (size_t)3 * BB * SS * EE / 4;
        split_x<<<(unsigned)((nx + 255) / 256), 256>>>(Xk, Xv, Xq);
        size_t nw = (size_t)3 * HH * HD * EE;
        split_w<<<(unsigned)((nw + 255) / 256), 256>>>(Wk, Wv, Wq);
        size_t no = (size_t)EE * EE;
        split_wo<<<(unsigned)((no + 255) / 256), 256>>>(Wo);
    }

    proj_tc<<<dim3(2, SS/128, 3*BH), 256, SMEM_MMA>>>(0);
    score_tc<<<dim3(SS/128, SS/128, BH), 256, SMEM_MMA>>>();
    softmax_kernel<<<(BH*SS + 7) / 8, 256>>>();
    av_tc<<<dim3(HD/128, SS/128, BH), 256, SMEM_MMA>>>();
    outproj_tc<<<dim3(EE/128, (BB*SS)/128, 1), 256, SMEM_MMA>>>(bo, out);
}

// round 10
// speedup vs baseline: 2.4664x; 1.0997x over previous
#include <cuda_runtime.h>
#include <cuda_bf16.h>
#include <math.h>
#include <stdint.h>

// Problem dims
#define BB 4
#define SS 2048
#define EE 768
#define HH 3
#define HD 256
#define BH (BB*HH)        // 12

// ---------------- device scratch (no allocation allowed) -------------------
__device__ float g_Sc[(size_t)BH*SS*SS];   // fp32 scores (causal half used)
// bf16 hi/lo split operands
__device__ __align__(256) __nv_bfloat16 g_Xhi[(size_t)3*BB*SS*EE];   // inputs [t][b][s][e]
__device__ __align__(256) __nv_bfloat16 g_Xlo[(size_t)3*BB*SS*EE];
__device__ __align__(256) __nv_bfloat16 g_Wthi[(size_t)3*HH*HD*EE]; // W^T [t][h][n][k]
__device__ __align__(256) __nv_bfloat16 g_Wtlo[(size_t)3*HH*HD*EE];
__device__ __align__(256) __nv_bfloat16 g_WoThi[(size_t)EE*EE];     // Wo^T [n][k]
__device__ __align__(256) __nv_bfloat16 g_WoTlo[(size_t)EE*EE];
__device__ __align__(256) __nv_bfloat16 g_Qhi[(size_t)BH*SS*HD];
__device__ __align__(256) __nv_bfloat16 g_Qlo[(size_t)BH*SS*HD];
__device__ __align__(256) __nv_bfloat16 g_Khi[(size_t)BH*SS*HD];
__device__ __align__(256) __nv_bfloat16 g_Klo[(size_t)BH*SS*HD];
__device__ __align__(256) __nv_bfloat16 g_Vthi[(size_t)BH*HD*SS];  // V^T [bh][f][k]
__device__ __align__(256) __nv_bfloat16 g_Vtlo[(size_t)BH*HD*SS];
__device__ __align__(256) __nv_bfloat16 g_Phi[(size_t)BH*SS*SS];   // probs hi
__device__ __align__(256) __nv_bfloat16 g_Plo[(size_t)BH*SS*SS];   // probs lo
__device__ __align__(256) __nv_bfloat16 g_Ohi[(size_t)BB*SS*EE];   // attn out concat
__device__ __align__(256) __nv_bfloat16 g_Olo[(size_t)BB*SS*EE];

__device__ __forceinline__ void splt(float x, __nv_bfloat16& h, __nv_bfloat16& l) {
    h = __float2bfloat16(x);
    l = __float2bfloat16(x - __bfloat162float(h));
}

// =========================== mma.sync machinery ============================
#define CHUNK 32
#define OPSZ  8192       // bytes: one operand per stage (2 k16-panels x 4KB)
#define BUFSZ 32768      // 4 operands per stage
#define STAGES 3
#define SMEM_MMA (STAGES*BUFSZ)   // 98304

__device__ __forceinline__ uint32_t smem_u32(const void* p) {
    uint32_t a;
    asm("{ .reg .u64 t; cvta.to.shared.u64 t, %1; cvt.u32.u64 %0, t; }" : "=r"(a) : "l"(p));
    return a;
}
#define CP16(saddr, gptr) \
    asm volatile("cp.async.cg.shared.global [%0], [%1], 16;" :: "r"(saddr), "l"(gptr))
#define CP_COMMIT() asm volatile("cp.async.commit_group;" ::: "memory")
#define CP_WAIT(n)  asm volatile("cp.async.wait_group %0;" :: "n"(n) : "memory")

#define MMA(c, a, b) \
    asm volatile("mma.sync.aligned.m16n8k16.row.col.f32.bf16.bf16.f32 " \
        "{%0,%1,%2,%3}, {%4,%5,%6,%7}, {%8,%9}, {%0,%1,%2,%3};" \
        : "+f"((c)[0]), "+f"((c)[1]), "+f"((c)[2]), "+f"((c)[3]) \
        : "r"((a)[0]), "r"((a)[1]), "r"((a)[2]), "r"((a)[3]), \
          "r"((b)[0]), "r"((b)[1]))

#define LDSM4(r0, r1, r2, r3, addr) \
    asm volatile("ldmatrix.sync.aligned.m8n8.x4.shared.b16 {%0,%1,%2,%3}, [%4];" \
        : "=r"(r0), "=r"(r1), "=r"(r2), "=r"(r3) : "r"(addr))

// issue cp.async for one 128x32 chunk of all 4 operands into stage `buf`
__device__ __forceinline__ void issue_chunk(uint32_t sb, int buf,
    const __nv_bfloat16* Ahi, const __nv_bfloat16* Alo, size_t lda,
    const __nv_bfloat16* Bhi, const __nv_bfloat16* Blo, size_t ldb,
    int kc, int tid)
{
    const __nv_bfloat16* gp[4] = {Ahi, Alo, Bhi, Blo};
    size_t lds_[4] = {lda, lda, ldb, ldb};
    #pragma unroll
    for (int op = 0; op < 4; op++) {
        #pragma unroll
        for (int i = 0; i < 2; i++) {
            int j = tid + (i << 8);
            int row = j >> 2, panel = (j >> 1) & 1, half = j & 1;
            const void* g = gp[op] + (size_t)row * lds_[op] + kc * CHUNK + panel * 16 + half * 8;
            uint32_t s = sb + buf * BUFSZ + op * OPSZ + panel * 4096
                       + (row << 5) + ((half ^ ((row >> 2) & 1)) << 4);
            CP16(s, g);
        }
    }
}

// 3-term split compute over one staged chunk, fragments via ldmatrix.x4
__device__ __forceinline__ void compute_chunk(uint32_t pb, uint32_t offA0, uint32_t offB0,
                                              float acc[4][4][4])
{
    #pragma unroll
    for (int p = 0; p < 2; p++) {
        uint32_t Ah = pb + p * 4096;
        uint32_t Al = Ah + OPSZ;
        uint32_t Bh = Ah + 2 * OPSZ;
        uint32_t Bl = Ah + 3 * OPSZ;
        uint32_t a[4][4], b[4][2], c[4][2];
        #pragma unroll
        for (int mi = 0; mi < 4; mi++)
            LDSM4(a[mi][0], a[mi][1], a[mi][2], a[mi][3], Ah + offA0 + (mi << 9));
        #pragma unroll
        for (int j = 0; j < 2; j++)
            LDSM4(b[2*j][0], b[2*j][1], b[2*j+1][0], b[2*j+1][1], Bh + offB0 + (j << 9));
        #pragma unroll
        for (int mi = 0; mi < 4; mi++)
            #pragma unroll
            for (int ni = 0; ni < 4; ni++) MMA(acc[mi][ni], a[mi], b[ni]);
        // A_hi x B_lo
        #pragma unroll
        for (int j = 0; j < 2; j++)
            LDSM4(c[2*j][0], c[2*j][1], c[2*j+1][0], c[2*j+1][1], Bl + offB0 + (j << 9));
        #pragma unroll
        for (int mi = 0; mi < 4; mi++)
            #pragma unroll
            for (int ni = 0; ni < 4; ni++) MMA(acc[mi][ni], a[mi], c[ni]);
        // A_lo x B_hi (reuse b, overwrite a)
        #pragma unroll
        for (int mi = 0; mi < 4; mi++)
            LDSM4(a[mi][0], a[mi][1], a[mi][2], a[mi][3], Al + offA0 + (mi << 9));
        #pragma unroll
        for (int mi = 0; mi < 4; mi++)
            #pragma unroll
            for (int ni = 0; ni < 4; ni++) MMA(acc[mi][ni], a[mi], b[ni]);
    }
}

__device__ __forceinline__ void mma_mainloop(uint32_t sb,
    const __nv_bfloat16* Ahi, const __nv_bfloat16* Alo, size_t lda,
    const __nv_bfloat16* Bhi, const __nv_bfloat16* Blo, size_t ldb,
    int nkc, float acc[4][4][4], int tid)
{
    int wid = tid >> 5, lane = tid & 31;
    int wm = (wid >> 2) << 6, wn = (wid & 3) << 5;

    // per-lane ldmatrix row offsets (byte offsets within a 4KB panel)
    int mat = lane >> 3;
    int rA = wm + (lane & 7) + ((mat & 1) << 3);
    int hA = mat >> 1;
    uint32_t offA0 = (uint32_t)((rA << 5) + ((hA ^ ((rA >> 2) & 1)) << 4));
    int rB = wn + (lane & 7) + ((mat >> 1) << 3);
    int hB = mat & 1;
    uint32_t offB0 = (uint32_t)((rB << 5) + ((hB ^ ((rB >> 2) & 1)) << 4));

    issue_chunk(sb, 0, Ahi, Alo, lda, Bhi, Blo, ldb, 0, tid);
    CP_COMMIT();
    issue_chunk(sb, 1, Ahi, Alo, lda, Bhi, Blo, ldb, 1, tid);
    CP_COMMIT();

    for (int kc = 0; kc < nkc; kc++) {
        if (kc + 1 < nkc) { CP_WAIT(1); } else { CP_WAIT(0); }
        __syncthreads();
        if (kc + 2 < nkc) {
            issue_chunk(sb, (kc + 2) % STAGES, Ahi, Alo, lda, Bhi, Blo, ldb, kc + 2, tid);
            CP_COMMIT();
        }
        compute_chunk(sb + (kc % STAGES) * BUFSZ, offA0, offB0, acc);
    }
    __syncthreads();
}

// ---------------------------------------------------------------------------
// Split kernels (fp32 -> bf16 hi/lo)
// ---------------------------------------------------------------------------
__global__ __launch_bounds__(256) void split_x(
    const float* __restrict__ Xk, const float* __restrict__ Xv, const float* __restrict__ Xq)
{
    const size_t N4 = (size_t)BB * SS * EE / 4;
    size_t i = (size_t)blockIdx.x * blockDim.x + threadIdx.x;
    if (i >= 3 * N4) return;
    int t = (int)(i / N4);
    size_t j = (i % N4) * 4;
    const float* X = (t == 0) ? Xk : (t == 1) ? Xv : Xq;
    float4 v = *(const float4*)(X + j);
    __nv_bfloat16 h[4], l[4];
    splt(v.x, h[0], l[0]); splt(v.y, h[1], l[1]);
    splt(v.z, h[2], l[2]); splt(v.w, h[3], l[3]);
    size_t o = (size_t)t * BB * SS * EE + j;
    *(uint2*)&g_Xhi[o] = *(uint2*)h;
    *(uint2*)&g_Xlo[o] = *(uint2*)l;
}

__global__ __launch_bounds__(256) void split_w(
    const float* __restrict__ Wk, const float* __restrict__ Wv, const float* __restrict__ Wq)
{
    size_t id = (size_t)blockIdx.x * blockDim.x + threadIdx.x;
    const size_t tot = (size_t)3 * HH * HD * EE;
    if (id >= tot) return;
    int k = (int)(id % EE);
    int n = (int)((id / EE) % HD);
    int h = (int)((id / ((size_t)EE * HD)) % HH);
    int t = (int)(id / ((size_t)EE * HD * HH));
    const float* W = (t == 0) ? Wk : (t == 1) ? Wv : Wq;
    float x = __ldg(&W[(size_t)h * EE * HD + (size_t)k * HD + n]);
    splt(x, g_Wthi[id], g_Wtlo[id]);
}

__global__ __launch_bounds__(256) void split_wo(const float* __restrict__ Wo)
{
    size_t id = (size_t)blockIdx.x * blockDim.x + threadIdx.x;
    if (id >= (size_t)EE * EE) return;
    int k = (int)(id % EE), n = (int)(id / EE);
    float x = __ldg(&Wo[(size_t)k * EE + n]);
    splt(x, g_WoThi[id], g_WoTlo[id]);
}

// ---------------------------------------------------------------------------
// Kernel 1 (TC): QKV projections.  grid (2, 16, 36): z = t*12 + bh
// ---------------------------------------------------------------------------
__global__ __launch_bounds__(256, 2) void proj_tc(int dummy)
{
    int z = blockIdx.z, nt = blockIdx.x, mt = blockIdx.y;
    int t = z / BH, bh = z % BH;
    int b = bh / HH, h = bh % HH;
    extern __shared__ char sm[];
    uint32_t sb = smem_u32(sm);
    int tid = threadIdx.x;

    float acc[4][4][4] = {};
    const __nv_bfloat16* Ahi = g_Xhi + ((size_t)t * BB + b) * SS * EE + (size_t)mt * 128 * EE;
    const __nv_bfloat16* Alo = g_Xlo + ((size_t)t * BB + b) * SS * EE + (size_t)mt * 128 * EE;
    const __nv_bfloat16* Bhi = g_Wthi + (((size_t)t * HH + h) * HD + (size_t)nt * 128) * EE;
    const __nv_bfloat16* Blo = g_Wtlo + (((size_t)t * HH + h) * HD + (size_t)nt * 128) * EE;
    mma_mainloop(sb, Ahi, Alo, EE, Bhi, Blo, EE, EE / CHUNK, acc, tid);

    int wid = tid >> 5, lane = tid & 31, g = lane >> 2, tq = lane & 3;
    int wm = (wid >> 2) << 6, wn = (wid & 3) << 5;

    if (t == 1) {
        // V: transposed bf16 hi/lo [bh][f][q]
        __nv_bfloat16* Vh = g_Vthi + (size_t)bh * HD * SS;
        __nv_bfloat16* Vl = g_Vtlo + (size_t)bh * HD * SS;
        #pragma unroll
        for (int mi = 0; mi < 4; mi++) {
            int q = mt * 128 + wm + mi * 16 + g;
            #pragma unroll
            for (int ni = 0; ni < 4; ni++) {
                int f = nt * 128 + wn + ni * 8 + 2 * tq;
                __nv_bfloat16 hh, ll;
                splt(acc[mi][ni][0], hh, ll); Vh[(size_t)f*SS + q] = hh; Vl[(size_t)f*SS + q] = ll;
                splt(acc[mi][ni][1], hh, ll); Vh[(size_t)(f+1)*SS + q] = hh; Vl[(size_t)(f+1)*SS + q] = ll;
                splt(acc[mi][ni][2], hh, ll); Vh[(size_t)f*SS + q + 8] = hh; Vl[(size_t)f*SS + q + 8] = ll;
                splt(acc[mi][ni][3], hh, ll); Vh[(size_t)(f+1)*SS + q + 8] = hh; Vl[(size_t)(f+1)*SS + q + 8] = ll;
            }
        }
    } else {
        __nv_bfloat16* Dh = ((t == 0) ? g_Khi : g_Qhi) + (size_t)bh * SS * HD;
        __nv_bfloat16* Dl = ((t == 0) ? g_Klo : g_Qlo) + (size_t)bh * SS * HD;
        #pragma unroll
        for (int mi = 0; mi < 4; mi++) {
            int s = mt * 128 + wm + mi * 16 + g;
            #pragma unroll
            for (int ni = 0; ni < 4; ni++) {
                int f = nt * 128 + wn + ni * 8 + 2 * tq;
                __nv_bfloat162 hp, lp;
                splt(acc[mi][ni][0], hp.x, lp.x); splt(acc[mi][ni][1], hp.y, lp.y);
                *(__nv_bfloat162*)&Dh[(size_t)s * HD + f] = hp;
                *(__nv_bfloat162*)&Dl[(size_t)s * HD + f] = lp;
                splt(acc[mi][ni][2], hp.x, lp.x); splt(acc[mi][ni][3], hp.y, lp.y);
                *(__nv_bfloat162*)&Dh[(size_t)(s + 8) * HD + f] = hp;
                *(__nv_bfloat162*)&Dl[(size_t)(s + 8) * HD + f] = lp;
            }
        }
    }
}

// ---------------------------------------------------------------------------
// Kernel 2 (TC): causal scores S = Q K^T / sqrt(S).  grid (16,16,12)
// ---------------------------------------------------------------------------
__global__ __launch_bounds__(256, 2) void score_tc()
{
    int bh = blockIdx.z, mt = blockIdx.y, nt = blockIdx.x;
    if (nt > mt) return;
    extern __shared__ char sm[];
    uint32_t sb = smem_u32(sm);
    int tid = threadIdx.x;

    float acc[4][4][4] = {};
    size_t ao = ((size_t)bh * SS + (size_t)mt * 128) * HD;
    size_t bo_ = ((size_t)bh * SS + (size_t)nt * 128) * HD;
    mma_mainloop(sb, g_Qhi + ao, g_Qlo + ao, HD,
                 g_Khi + bo_, g_Klo + bo_, HD, HD / CHUNK, acc, tid);

    int wid = tid >> 5, lane = tid & 31, g = lane >> 2, t = lane & 3;
    int wm = (wid >> 2) << 6, wn = (wid & 3) << 5;
    float* Sp = g_Sc + (size_t)bh * SS * SS;
    const float isc = 0.022097086912079608f;   // 1/sqrt(2048)

    #pragma unroll
    for (int mi = 0; mi < 4; mi++) {
        int gr = mt * 128 + wm + mi * 16 + g;
        #pragma unroll
        for (int ni = 0; ni < 4; ni++) {
            int gc = nt * 128 + wn + ni * 8 + 2 * t;
            *(float2*)&Sp[(size_t)gr * SS + gc] =
                make_float2(acc[mi][ni][0] * isc, acc[mi][ni][1] * isc);
            *(float2*)&Sp[(size_t)(gr + 8) * SS + gc] =
                make_float2(acc[mi][ni][2] * isc, acc[mi][ni][3] * isc);
        }
    }
}

// ---------------------------------------------------------------------------
// Kernel 3: warp-per-row causal softmax -> bf16 hi/lo probs, 128-aligned fill
// ---------------------------------------------------------------------------
__global__ __launch_bounds__(256) void softmax_kernel()
{
    int gwarp = (blockIdx.x * blockDim.x + threadIdx.x) >> 5;
    int lane  = threadIdx.x & 31;
    if (gwarp >= BH * SS) return;

    int bh = gwarp / SS;
    int r  = gwarp % SS;
    const float* sp = g_Sc + (size_t)bh * SS * SS + (size_t)r * SS;
    size_t pb = (size_t)bh * SS * SS + (size_t)r * SS;
    int n = r + 1;

    float mx = -3.0e38f;
    for (int j = lane; j < n; j += 32) mx = fmaxf(mx, sp[j]);
    #pragma unroll
    for (int o = 16; o; o >>= 1) mx = fmaxf(mx, __shfl_xor_sync(0xffffffffu, mx, o));

    float sum = 0.f;
    for (int j = lane; j < n; j += 32) sum += __expf(sp[j] - mx);
    #pragma unroll
    for (int o = 16; o; o >>= 1) sum += __shfl_xor_sync(0xffffffffu, sum, o);

    float inv = 1.0f / sum;
    for (int j = lane; j < n; j += 32) {
        float p = __expf(sp[j] - mx) * inv;
        splt(p, g_Phi[pb + j], g_Plo[pb + j]);
    }

    __nv_bfloat16 zz = __float2bfloat16(0.0f);
    int nceil = ((n + 127) & ~127);
    for (int j = n + lane; j < nceil; j += 32) { g_Phi[pb + j] = zz; g_Plo[pb + j] = zz; }
}

// ---------------------------------------------------------------------------
// Kernel 4 (TC): O = P @ V^T-layout, causal K-bound -> concat bf16 hi/lo.
// grid (2,16,12)
// ---------------------------------------------------------------------------
__global__ __launch_bounds__(256, 2) void av_tc()
{
    int bh = blockIdx.z, mt = blockIdx.y, nt = blockIdx.x;
    extern __shared__ char sm[];
    uint32_t sb = smem_u32(sm);
    int tid = threadIdx.x;

    float acc[4][4][4] = {};
    size_t ao = ((size_t)bh * SS + (size_t)mt * 128) * SS;
    size_t bo_ = ((size_t)bh * HD + (size_t)nt * 128) * SS;
    mma_mainloop(sb, g_Phi + ao, g_Plo + ao, SS,
                 g_Vthi + bo_, g_Vtlo + bo_, SS, (mt + 1) * (128 / CHUNK), acc, tid);

    int wid = tid >> 5, lane = tid & 31, g = lane >> 2, t = lane & 3;
    int wm = (wid >> 2) << 6, wn = (wid & 3) << 5;
    int b = bh / HH, h = bh % HH;

    #pragma unroll
    for (int mi = 0; mi < 4; mi++) {
        size_t row = (size_t)b * SS + mt * 128 + wm + mi * 16 + g;
        #pragma unroll
        for (int ni = 0; ni < 4; ni++) {
            int col = h * HD + nt * 128 + wn + ni * 8 + 2 * t;
            __nv_bfloat162 hp, lp;
            splt(acc[mi][ni][0], hp.x, lp.x); splt(acc[mi][ni][1], hp.y, lp.y);
            *(__nv_bfloat162*)&g_Ohi[row * EE + col] = hp;
            *(__nv_bfloat162*)&g_Olo[row * EE + col] = lp;
            splt(acc[mi][ni][2], hp.x, lp.x); splt(acc[mi][ni][3], hp.y, lp.y);
            *(__nv_bfloat162*)&g_Ohi[(row + 8) * EE + col] = hp;
            *(__nv_bfloat162*)&g_Olo[(row + 8) * EE + col] = lp;
        }
    }
}

// ---------------------------------------------------------------------------
// Kernel 5 (TC): Y = concat @ Wo + bo.  grid (6, 64)
// ---------------------------------------------------------------------------
__global__ __launch_bounds__(256, 2) void outproj_tc(
    const float* __restrict__ bo, float* __restrict__ Y)
{
    int nt = blockIdx.x, mt = blockIdx.y;
    extern __shared__ char sm[];
    uint32_t sb = smem_u32(sm);
    int tid = threadIdx.x;

    float acc[4][4][4] = {};
    const __nv_bfloat16* Ahi = g_Ohi + (size_t)mt * 128 * EE;
    const __nv_bfloat16* Alo = g_Olo + (size_t)mt * 128 * EE;
    const __nv_bfloat16* Bhi = g_WoThi + (size_t)nt * 128 * EE;
    const __nv_bfloat16* Blo = g_WoTlo + (size_t)nt * 128 * EE;
    mma_mainloop(sb, Ahi, Alo, EE, Bhi, Blo, EE, EE / CHUNK, acc, tid);

    int wid = tid >> 5, lane = tid & 31, g = lane >> 2, t = lane & 3;
    int wm = (wid >> 2) << 6, wn = (wid & 3) << 5;

    #pragma unroll
    for (int mi = 0; mi < 4; mi++) {
        size_t gr = (size_t)mt * 128 + wm + mi * 16 + g;
        #pragma unroll
        for (int ni = 0; ni < 4; ni++) {
            int gc = nt * 128 + wn + ni * 8 + 2 * t;
            float bx = bo[gc], by = bo[gc + 1];
            *(float2*)&Y[gr * EE + gc] =
                make_float2(acc[mi][ni][0] + bx, acc[mi][ni][1] + by);
            *(float2*)&Y[(gr + 8) * EE + gc] =
                make_float2(acc[mi][ni][2] + bx, acc[mi][ni][3] + by);
        }
    }
}

// ---------------------------------------------------------------------------
extern "C" void kernel_launch(void* const* d_in, const int* in_sizes, int n_in,
                              void* d_out, int out_size)
{
    const float* Xk = (const float*)d_in[0];
    const float* Xv = (const float*)d_in[1];
    const float* Xq = (const float*)d_in[2];
    const float* Wk = (const float*)d_in[3];
    const float* Wv = (const float*)d_in[4];
    const float* Wq = (const float*)d_in[5];
    const float* Wo = (const float*)d_in[6];
    const float* bo = (const float*)d_in[7];
    float* out = (float*)d_out;

    cudaFuncSetAttribute(proj_tc,    cudaFuncAttributeMaxDynamicSharedMemorySize, SMEM_MMA);
    cudaFuncSetAttribute(score_tc,   cudaFuncAttributeMaxDynamicSharedMemorySize, SMEM_MMA);
    cudaFuncSetAttribute(av_tc,      cudaFuncAttributeMaxDynamicSharedMemorySize, SMEM_MMA);
    cudaFuncSetAttribute(outproj_tc, cudaFuncAttributeMaxDynamicSharedMemorySize, SMEM_MMA);

    {   // splits
        size_t nx = (size_t)3 * BB * SS * EE / 4;
        split_x<<<(unsigned)((nx + 255) / 256), 256>>>(Xk, Xv, Xq);
        size_t nw = (size_t)3 * HH * HD * EE;
        split_w<<<(unsigned)((nw + 255) / 256), 256>>>(Wk, Wv, Wq);
        size_t no = (size_t)EE * EE;
        split_wo<<<(unsigned)((no + 255) / 256), 256>>>(Wo);
    }

    proj_tc<<<dim3(2, SS/128, 3*BH), 256, SMEM_MMA>>>(0);
    score_tc<<<dim3(SS/128, SS/128, BH), 256, SMEM_MMA>>>();
    softmax_kernel<<<(BH*SS + 7) / 8, 256>>>();
    av_tc<<<dim3(HD/128, SS/128, BH), 256, SMEM_MMA>>>();
    outproj_tc<<<dim3(EE/128, (BB*SS)/128, 1), 256, SMEM_MMA>>>(bo, out);
}